// round 12
// baseline (speedup 1.0000x reference)
#include <cuda_runtime.h>
#include <cuda_bf16.h>
#include <math.h>

#define NV 50000
#define NE 600000
#define NM 100000
#define IN_CH 256
#define HC 256
#define NH 8

#define SCAN_CHUNK 4096
#define NBLK_E ((NM + SCAN_CHUNK - 1) / SCAN_CHUNK)   // 25
#define NBLK_V ((NV + SCAN_CHUNK - 1) / SCAN_CHUNK)   // 13

// ---------------- scratch (device globals) ----------------
__device__ float g_X0[NV * HC];        // X @ W
__device__ float g_Xe[NM * HC];        // hyperedge feature MEANS
__device__ float g_alphae[NM * NH];    // per-hyperedge logits
__device__ int   g_cntE[NM], g_cntV[NV];
__device__ int   g_startE[NM + 1], g_startV[NV + 1];
__device__ int   g_curE[NM], g_curV[NV];
__device__ int   g_incE[NE];
__device__ int   g_incV[NE];
__device__ int   g_blkSumE[NBLK_E], g_blkSumV[NBLK_V];
__device__ int   g_blkOffE[NBLK_E], g_blkOffV[NBLK_V];
__device__ unsigned g_Wt_hi[HC * (IN_CH / 2)];
__device__ unsigned g_Wt_lo[HC * (IN_CH / 2)];

// ---------------- split helper: two floats -> packed bf16x2 hi + lo ----------------
__device__ __forceinline__ void split2(float x, float y, unsigned& h, unsigned& l) {
    __nv_bfloat16 hx = __float2bfloat16_rn(x);
    __nv_bfloat16 hy = __float2bfloat16_rn(y);
    float lxf = x - __bfloat162float(hx);
    float lyf = y - __bfloat162float(hy);
    __nv_bfloat16 lx = __float2bfloat16_rn(lxf);
    __nv_bfloat16 ly = __float2bfloat16_rn(lyf);
    h = ((unsigned)__bfloat16_as_ushort(hy) << 16) | (unsigned)__bfloat16_as_ushort(hx);
    l = ((unsigned)__bfloat16_as_ushort(ly) << 16) | (unsigned)__bfloat16_as_ushort(lx);
}

// ---------------- prep: split + transpose W ----------------
__global__ void k_prepW(const float* __restrict__ W) {
    int idx = blockIdx.x * blockDim.x + threadIdx.x;
    if (idx >= HC * (IN_CH / 2)) return;
    int n = idx >> 7, p = idx & 127;
    float x = __ldg(&W[(2 * p) * HC + n]);
    float y = __ldg(&W[(2 * p + 1) * HC + n]);
    unsigned h, l;
    split2(x, y, h, l);
    g_Wt_hi[idx] = h;
    g_Wt_lo[idx] = l;
}

#define MMA_BF16(C, A, B)                                                     \
    asm volatile(                                                             \
        "mma.sync.aligned.m16n8k16.row.col.f32.bf16.bf16.f32 "                \
        "{%0,%1,%2,%3}, {%4,%5,%6,%7}, {%8,%9}, {%0,%1,%2,%3};"               \
        : "+f"(C[0]), "+f"(C[1]), "+f"(C[2]), "+f"(C[3])                      \
        : "r"(A[0]), "r"(A[1]), "r"(A[2]), "r"(A[3]), "r"(B[0]), "r"(B[1]))

// ---------------- tensor-core GEMM: g_X0 = X @ W, 3-term split-bf16 ----------------
__global__ __launch_bounds__(256) void k_gemm(const float* __restrict__ A) {
    __shared__ unsigned As_h[128][17], As_l[128][17];
    __shared__ unsigned Bs_h[128][17], Bs_l[128][17];

    const int tid = threadIdx.x;
    const int wid = tid >> 5, lane = tid & 31;
    const int g = lane >> 2, t = lane & 3;
    const int warpM = wid & 3, warpN = wid >> 2;
    const int rowBase = blockIdx.y * 128;
    const int colBase = blockIdx.x * 128;

    float c[2][8][4];
#pragma unroll
    for (int mt = 0; mt < 2; mt++)
#pragma unroll
        for (int nt = 0; nt < 8; nt++)
#pragma unroll
            for (int r = 0; r < 4; r++) c[mt][nt][r] = 0.f;

    const int lrow = tid >> 1;
    const int lko  = (tid & 1) * 16;
    const int lpo  = (tid & 1) * 8;
    const bool aval = (rowBase + lrow) < NV;
    const float* aBase = A + (size_t)(rowBase + lrow) * IN_CH + lko;
    const int bn = tid >> 1;

    for (int k0 = 0; k0 < IN_CH; k0 += 32) {
#pragma unroll
        for (int j = 0; j < 4; j++) {
            float4 v = make_float4(0.f, 0.f, 0.f, 0.f);
            if (aval) v = *(const float4*)(aBase + k0 + j * 4);
            unsigned h0, l0, h1, l1;
            split2(v.x, v.y, h0, l0);
            split2(v.z, v.w, h1, l1);
            As_h[lrow][lpo + j * 2]     = h0;
            As_h[lrow][lpo + j * 2 + 1] = h1;
            As_l[lrow][lpo + j * 2]     = l0;
            As_l[lrow][lpo + j * 2 + 1] = l1;
        }
        {
            int p0 = k0 >> 1;
            const unsigned* src_h = &g_Wt_hi[(size_t)(colBase + bn) * 128 + p0 + lpo];
            const unsigned* src_l = &g_Wt_lo[(size_t)(colBase + bn) * 128 + p0 + lpo];
            uint4 h0 = ((const uint4*)src_h)[0];
            uint4 h1 = ((const uint4*)src_h)[1];
            uint4 l0 = ((const uint4*)src_l)[0];
            uint4 l1 = ((const uint4*)src_l)[1];
            Bs_h[bn][lpo + 0] = h0.x; Bs_h[bn][lpo + 1] = h0.y;
            Bs_h[bn][lpo + 2] = h0.z; Bs_h[bn][lpo + 3] = h0.w;
            Bs_h[bn][lpo + 4] = h1.x; Bs_h[bn][lpo + 5] = h1.y;
            Bs_h[bn][lpo + 6] = h1.z; Bs_h[bn][lpo + 7] = h1.w;
            Bs_l[bn][lpo + 0] = l0.x; Bs_l[bn][lpo + 1] = l0.y;
            Bs_l[bn][lpo + 2] = l0.z; Bs_l[bn][lpo + 3] = l0.w;
            Bs_l[bn][lpo + 4] = l1.x; Bs_l[bn][lpo + 5] = l1.y;
            Bs_l[bn][lpo + 6] = l1.z; Bs_l[bn][lpo + 7] = l1.w;
        }
        __syncthreads();

#pragma unroll
        for (int s = 0; s < 2; s++) {
            const int pb = s * 8;
            unsigned ah[2][4], al[2][4];
#pragma unroll
            for (int mt = 0; mt < 2; mt++) {
                int r = warpM * 32 + mt * 16;
                ah[mt][0] = As_h[r + g][pb + t];
                ah[mt][1] = As_h[r + g + 8][pb + t];
                ah[mt][2] = As_h[r + g][pb + t + 4];
                ah[mt][3] = As_h[r + g + 8][pb + t + 4];
                al[mt][0] = As_l[r + g][pb + t];
                al[mt][1] = As_l[r + g + 8][pb + t];
                al[mt][2] = As_l[r + g][pb + t + 4];
                al[mt][3] = As_l[r + g + 8][pb + t + 4];
            }
            unsigned bh[8][2], bl[8][2];
#pragma unroll
            for (int nt = 0; nt < 8; nt++) {
                int n = warpN * 64 + nt * 8 + g;
                bh[nt][0] = Bs_h[n][pb + t];
                bh[nt][1] = Bs_h[n][pb + t + 4];
                bl[nt][0] = Bs_l[n][pb + t];
                bl[nt][1] = Bs_l[n][pb + t + 4];
            }
#pragma unroll
            for (int mt = 0; mt < 2; mt++)
#pragma unroll
                for (int nt = 0; nt < 8; nt++) {
                    MMA_BF16(c[mt][nt], ah[mt], bh[nt]);
                    MMA_BF16(c[mt][nt], ah[mt], bl[nt]);
                    MMA_BF16(c[mt][nt], al[mt], bh[nt]);
                }
        }
        __syncthreads();
    }

#pragma unroll
    for (int mt = 0; mt < 2; mt++) {
        int r0 = rowBase + warpM * 32 + mt * 16 + g;
#pragma unroll
        for (int nt = 0; nt < 8; nt++) {
            int cc = colBase + warpN * 64 + nt * 8 + 2 * t;
            if (r0 < NV)
                *(float2*)&g_X0[(size_t)r0 * HC + cc] = make_float2(c[mt][nt][0], c[mt][nt][1]);
            if (r0 + 8 < NV)
                *(float2*)&g_X0[(size_t)(r0 + 8) * HC + cc] = make_float2(c[mt][nt][2], c[mt][nt][3]);
        }
    }
}

// ---------------- init / histogram / scan / fill ----------------
__global__ void k_init() {
    int i = blockIdx.x * blockDim.x + threadIdx.x;
    if (i < NM) g_cntE[i] = 0;
    if (i < NV) g_cntV[i] = 0;
}

__global__ void k_hist(const int* __restrict__ vertex, const int* __restrict__ edges) {
    int e = blockIdx.x * blockDim.x + threadIdx.x;
    if (e >= NE) return;
    atomicAdd(&g_cntE[__ldg(&edges[e])], 1);
    atomicAdd(&g_cntV[__ldg(&vertex[e])], 1);
}

__global__ void k_scanA() {
    bool isE = (blockIdx.x < NBLK_E);
    int lb = isE ? blockIdx.x : blockIdx.x - NBLK_E;
    int n = isE ? NM : NV;
    const int* cnt = isE ? g_cntE : g_cntV;
    int* blkSum = isE ? g_blkSumE : g_blkSumV;

    int i4 = lb * 1024 + threadIdx.x;
    int s = 0;
    if (i4 * 4 < n) {
        int4 c = ((const int4*)cnt)[i4];
        s = c.x + c.y + c.z + c.w;
    }
    __shared__ int ws[32];
    int lane = threadIdx.x & 31, wid = threadIdx.x >> 5;
#pragma unroll
    for (int o = 16; o > 0; o >>= 1) s += __shfl_xor_sync(0xffffffffu, s, o);
    if (lane == 0) ws[wid] = s;
    __syncthreads();
    if (wid == 0) {
        int tv = ws[lane];
#pragma unroll
        for (int o = 16; o > 0; o >>= 1) tv += __shfl_xor_sync(0xffffffffu, tv, o);
        if (lane == 0) blkSum[lb] = tv;
    }
}

__global__ void k_scanB() {
    int lane = threadIdx.x & 31, wid = threadIdx.x >> 5;
    if (wid == 0) {
        int v = (lane < NBLK_E) ? g_blkSumE[lane] : 0;
        int incl = v;
#pragma unroll
        for (int o = 1; o < 32; o <<= 1) {
            int t = __shfl_up_sync(0xffffffffu, incl, o);
            if (lane >= o) incl += t;
        }
        if (lane < NBLK_E) g_blkOffE[lane] = incl - v;
        if (lane == 31) g_startE[NM] = incl;
    } else if (wid == 1) {
        int v = (lane < NBLK_V) ? g_blkSumV[lane] : 0;
        int incl = v;
#pragma unroll
        for (int o = 1; o < 32; o <<= 1) {
            int t = __shfl_up_sync(0xffffffffu, incl, o);
            if (lane >= o) incl += t;
        }
        if (lane < NBLK_V) g_blkOffV[lane] = incl - v;
        if (lane == 31) g_startV[NV] = incl;
    }
}

__global__ void k_scanC() {
    bool isE = (blockIdx.x < NBLK_E);
    int lb = isE ? blockIdx.x : blockIdx.x - NBLK_E;
    int n = isE ? NM : NV;
    const int* cnt = isE ? g_cntE : g_cntV;
    int* start = isE ? g_startE : g_startV;
    int* cur   = isE ? g_curE : g_curV;
    int blkOff = isE ? g_blkOffE[lb] : g_blkOffV[lb];

    int i4 = lb * 1024 + threadIdx.x;
    int4 c = make_int4(0, 0, 0, 0);
    if (i4 * 4 < n) c = ((const int4*)cnt)[i4];
    int tsum = c.x + c.y + c.z + c.w;

    __shared__ int ws[32];
    int lane = threadIdx.x & 31, wid = threadIdx.x >> 5;
    int incl = tsum;
#pragma unroll
    for (int o = 1; o < 32; o <<= 1) {
        int t = __shfl_up_sync(0xffffffffu, incl, o);
        if (lane >= o) incl += t;
    }
    if (lane == 31) ws[wid] = incl;
    __syncthreads();
    if (wid == 0) {
        int w = ws[lane];
#pragma unroll
        for (int o = 1; o < 32; o <<= 1) {
            int t = __shfl_up_sync(0xffffffffu, w, o);
            if (lane >= o) w += t;
        }
        ws[lane] = w;
    }
    __syncthreads();
    int excl = incl - tsum + (wid > 0 ? ws[wid - 1] : 0) + blkOff;

    if (i4 * 4 < n) {
        int4 st;
        st.x = excl;
        st.y = st.x + c.x;
        st.z = st.y + c.y;
        st.w = st.z + c.z;
        ((int4*)start)[i4] = st;
        ((int4*)cur)[i4]   = st;
    }
}

__global__ void k_fill(const int* __restrict__ vertex, const int* __restrict__ edges) {
    int e = blockIdx.x * blockDim.x + threadIdx.x;
    if (e >= NE) return;
    int v  = __ldg(&vertex[e]);
    int ed = __ldg(&edges[e]);
    int pE = atomicAdd(&g_curE[ed], 1);
    g_incE[pE] = v;
    int pV = atomicAdd(&g_curV[v], 1);
    g_incV[pV] = ed;
}

#define ACC4(A, X, W)                                                       \
    A.x += X.x * W; A.y += X.y * W; A.z += X.z * W; A.w += X.w * W;

// ---------------- per-hyperedge aggregate (mean) + logits ----------------
// Coalesced: lane covers float4 index `lane` (head lane>>3) and `lane+32` (head 4+(lane>>3)).
__global__ void k_edge_agg(const float* __restrict__ att) {
    int m = (blockIdx.x * blockDim.x + threadIdx.x) >> 5;
    if (m >= NM) return;
    int lane = threadIdx.x & 31;
    int s0 = g_startE[m], s1 = g_startE[m + 1];

    float4 acc0 = make_float4(0.f, 0.f, 0.f, 0.f);
    float4 acc1 = make_float4(0.f, 0.f, 0.f, 0.f);
    int i = s0;
    for (; i + 2 <= s1; i += 2) {
        int v0 = __ldg(&g_incE[i]);
        int v1 = __ldg(&g_incE[i + 1]);
        const float4* xr0 = (const float4*)&g_X0[(size_t)v0 * HC];
        const float4* xr1 = (const float4*)&g_X0[(size_t)v1 * HC];
        float4 xa0 = __ldg(&xr0[lane]), xa1 = __ldg(&xr0[lane + 32]);
        float4 xb0 = __ldg(&xr1[lane]), xb1 = __ldg(&xr1[lane + 32]);
        ACC4(acc0, xa0, 1.0f); ACC4(acc1, xa1, 1.0f);
        ACC4(acc0, xb0, 1.0f); ACC4(acc1, xb1, 1.0f);
    }
    if (i < s1) {
        int v0 = __ldg(&g_incE[i]);
        const float4* xr0 = (const float4*)&g_X0[(size_t)v0 * HC];
        float4 xa0 = __ldg(&xr0[lane]), xa1 = __ldg(&xr0[lane + 32]);
        ACC4(acc0, xa0, 1.0f); ACC4(acc1, xa1, 1.0f);
    }

    float inv = 1.0f / fmaxf((float)(s1 - s0), 1.0f);
    acc0.x *= inv; acc0.y *= inv; acc0.z *= inv; acc0.w *= inv;
    acc1.x *= inv; acc1.y *= inv; acc1.z *= inv; acc1.w *= inv;

    float4* xe = (float4*)&g_Xe[(size_t)m * HC];
    xe[lane]      = acc0;
    xe[lane + 32] = acc1;

    const float4* at = (const float4*)att;
    float4 b0 = __ldg(&at[lane]), b1 = __ldg(&at[lane + 32]);
    float p0 = acc0.x * b0.x + acc0.y * b0.y + acc0.z * b0.z + acc0.w * b0.w;
    float p1 = acc1.x * b1.x + acc1.y * b1.y + acc1.z * b1.z + acc1.w * b1.w;
    // reduce within 8-lane head groups
#pragma unroll
    for (int o = 1; o <= 4; o <<= 1) {
        p0 += __shfl_xor_sync(0xffffffffu, p0, o);
        p1 += __shfl_xor_sync(0xffffffffu, p1, o);
    }
    if ((lane & 7) == 0) {
        g_alphae[m * NH + (lane >> 3)]     = p0;
        g_alphae[m * NH + 4 + (lane >> 3)] = p1;
    }
}

__device__ __forceinline__ float gelu1(float x) {
    return 0.5f * x * (1.0f + erff(x * 0.70710678118654752f));
}

// ---------------- single-pass per-vertex weighted gather + GELU ----------------
// Softmax computed unnormalized: out = (sum exp(a)*Xe) / (sum exp(a)).
// Logits are bounded (|a| < ~10) so exp never overflows; ratio == softmax exactly.
// Coalesced gather: lane covers float4 `lane` (head lane>>3) and `lane+32` (head 4+(lane>>3)).
__global__ void k_vertex(float* __restrict__ out) {
    int warp = (blockIdx.x * blockDim.x + threadIdx.x) >> 5;
    if (warp >= NV) return;
    int lane = threadIdx.x & 31;

    int v0i = g_startV[warp], v1i = g_startV[warp + 1];
    int deg = v1i - v0i;
    int h0 = lane >> 3;

    float4 acc0 = make_float4(0.f, 0.f, 0.f, 0.f);
    float4 acc1 = make_float4(0.f, 0.f, 0.f, 0.f);
    float se0 = 0.f, se1 = 0.f;      // per-head exp sums (redundant across 8-lane group)
    int i = 0;
    for (; i + 2 <= deg; i += 2) {
        int e0 = __ldg(&g_incV[v0i + i]);
        int e1 = __ldg(&g_incV[v0i + i + 1]);
        float aA0 = g_alphae[e0 * NH + h0];
        float aA1 = g_alphae[e0 * NH + 4 + h0];
        float aB0 = g_alphae[e1 * NH + h0];
        float aB1 = g_alphae[e1 * NH + 4 + h0];
        const float4* xr0 = (const float4*)&g_Xe[(size_t)e0 * HC];
        const float4* xr1 = (const float4*)&g_Xe[(size_t)e1 * HC];
        float4 xa0 = __ldg(&xr0[lane]), xa1 = __ldg(&xr0[lane + 32]);
        float4 xb0 = __ldg(&xr1[lane]), xb1 = __ldg(&xr1[lane + 32]);
        aA0 = aA0 >= 0.f ? aA0 : 0.2f * aA0;
        aA1 = aA1 >= 0.f ? aA1 : 0.2f * aA1;
        aB0 = aB0 >= 0.f ? aB0 : 0.2f * aB0;
        aB1 = aB1 >= 0.f ? aB1 : 0.2f * aB1;
        float wA0 = __expf(aA0);
        float wA1 = __expf(aA1);
        float wB0 = __expf(aB0);
        float wB1 = __expf(aB1);
        se0 += wA0 + wB0;
        se1 += wA1 + wB1;
        ACC4(acc0, xa0, wA0); ACC4(acc1, xa1, wA1);
        ACC4(acc0, xb0, wB0); ACC4(acc1, xb1, wB1);
    }
    if (i < deg) {
        int e0 = __ldg(&g_incV[v0i + i]);
        float aA0 = g_alphae[e0 * NH + h0];
        float aA1 = g_alphae[e0 * NH + 4 + h0];
        const float4* xr0 = (const float4*)&g_Xe[(size_t)e0 * HC];
        float4 xa0 = __ldg(&xr0[lane]), xa1 = __ldg(&xr0[lane + 32]);
        aA0 = aA0 >= 0.f ? aA0 : 0.2f * aA0;
        aA1 = aA1 >= 0.f ? aA1 : 0.2f * aA1;
        float wA0 = __expf(aA0);
        float wA1 = __expf(aA1);
        se0 += wA0;
        se1 += wA1;
        ACC4(acc0, xa0, wA0); ACC4(acc1, xa1, wA1);
    }

    float rs0 = 1.0f / (se0 + 1e-16f);
    float rs1 = 1.0f / (se1 + 1e-16f);
    acc0.x *= rs0; acc0.y *= rs0; acc0.z *= rs0; acc0.w *= rs0;
    acc1.x *= rs1; acc1.y *= rs1; acc1.z *= rs1; acc1.w *= rs1;

    acc0.x = gelu1(acc0.x); acc0.y = gelu1(acc0.y);
    acc0.z = gelu1(acc0.z); acc0.w = gelu1(acc0.w);
    acc1.x = gelu1(acc1.x); acc1.y = gelu1(acc1.y);
    acc1.z = gelu1(acc1.z); acc1.w = gelu1(acc1.w);

    float4* op = (float4*)&out[(size_t)warp * HC];
    op[lane]      = acc0;
    op[lane + 32] = acc1;
}

extern "C" void kernel_launch(void* const* d_in, const int* in_sizes, int n_in,
                              void* d_out, int out_size) {
    const float* X      = (const float*)d_in[0];
    const float* W      = (const float*)d_in[1];
    const float* att    = (const float*)d_in[2];
    const int*   vertex = (const int*)d_in[3];
    const int*   edges  = (const int*)d_in[4];
    float* out = (float*)d_out;

    static cudaStream_t s2 = nullptr;
    static cudaEvent_t evFork = nullptr, evJoin = nullptr;
    if (s2 == nullptr) {
        cudaStreamCreate(&s2);
        cudaEventCreateWithFlags(&evFork, cudaEventDisableTiming);
        cudaEventCreateWithFlags(&evJoin, cudaEventDisableTiming);
    }

    // fork: GEMM (tensor core) on side stream, concurrent with CSR build
    cudaEventRecord(evFork, 0);
    cudaStreamWaitEvent(s2, evFork, 0);
    k_prepW<<<(HC * (IN_CH / 2) + 255) / 256, 256, 0, s2>>>(W);
    {
        dim3 grid(HC / 128, (NV + 127) / 128);
        k_gemm<<<grid, 256, 0, s2>>>(X);
    }
    k_init<<<(NM + 255) / 256, 256>>>();
    k_hist<<<(NE + 255) / 256, 256>>>(vertex, edges);
    k_scanA<<<NBLK_E + NBLK_V, 1024>>>();
    k_scanB<<<1, 64>>>();
    k_scanC<<<NBLK_E + NBLK_V, 1024>>>();
    k_fill<<<(NE + 255) / 256, 256>>>(vertex, edges);
    // join: edge aggregation needs both X0 (s2) and CSR (main)
    cudaEventRecord(evJoin, s2);
    cudaStreamWaitEvent(0, evJoin, 0);

    k_edge_agg<<<(NM * 32 + 255) / 256, 256>>>(att);
    k_vertex<<<(NV * 32 + 255) / 256, 256>>>(out);
}

// round 13
// speedup vs baseline: 1.1662x; 1.1662x over previous
#include <cuda_runtime.h>
#include <cuda_bf16.h>
#include <cuda_fp16.h>
#include <math.h>

#define NV 50000
#define NE 600000
#define NM 100000
#define IN_CH 256
#define HC 256
#define NH 8

#define SCAN_CHUNK 4096
#define NBLK_E ((NM + SCAN_CHUNK - 1) / SCAN_CHUNK)   // 25
#define NBLK_V ((NV + SCAN_CHUNK - 1) / SCAN_CHUNK)   // 13

// ---------------- scratch (device globals) ----------------
__device__ float  g_X0[NV * HC];        // X @ W (fp32)
__device__ __half g_Xe[NM * HC];        // hyperedge feature MEANS (fp16)
__device__ float  g_alphae[NM * NH];    // per-hyperedge logits (fp32, from fp32 accs)
__device__ int    g_cntE[NM], g_cntV[NV];
__device__ int    g_startE[NM + 1], g_startV[NV + 1];
__device__ int    g_curE[NM], g_curV[NV];
__device__ int    g_incE[NE];
__device__ int    g_incV[NE];
__device__ int    g_blkSumE[NBLK_E], g_blkSumV[NBLK_V];
__device__ int    g_blkOffE[NBLK_E], g_blkOffV[NBLK_V];
__device__ unsigned g_Wt_hi[HC * (IN_CH / 2)];
__device__ unsigned g_Wt_lo[HC * (IN_CH / 2)];

// ---------------- split helper: two floats -> packed bf16x2 hi + lo ----------------
__device__ __forceinline__ void split2(float x, float y, unsigned& h, unsigned& l) {
    __nv_bfloat16 hx = __float2bfloat16_rn(x);
    __nv_bfloat16 hy = __float2bfloat16_rn(y);
    float lxf = x - __bfloat162float(hx);
    float lyf = y - __bfloat162float(hy);
    __nv_bfloat16 lx = __float2bfloat16_rn(lxf);
    __nv_bfloat16 ly = __float2bfloat16_rn(lyf);
    h = ((unsigned)__bfloat16_as_ushort(hy) << 16) | (unsigned)__bfloat16_as_ushort(hx);
    l = ((unsigned)__bfloat16_as_ushort(ly) << 16) | (unsigned)__bfloat16_as_ushort(lx);
}

// ---------------- prep: split + transpose W ----------------
__global__ void k_prepW(const float* __restrict__ W) {
    int idx = blockIdx.x * blockDim.x + threadIdx.x;
    if (idx >= HC * (IN_CH / 2)) return;
    int n = idx >> 7, p = idx & 127;
    float x = __ldg(&W[(2 * p) * HC + n]);
    float y = __ldg(&W[(2 * p + 1) * HC + n]);
    unsigned h, l;
    split2(x, y, h, l);
    g_Wt_hi[idx] = h;
    g_Wt_lo[idx] = l;
}

#define MMA_BF16(C, A, B)                                                     \
    asm volatile(                                                             \
        "mma.sync.aligned.m16n8k16.row.col.f32.bf16.bf16.f32 "                \
        "{%0,%1,%2,%3}, {%4,%5,%6,%7}, {%8,%9}, {%0,%1,%2,%3};"               \
        : "+f"(C[0]), "+f"(C[1]), "+f"(C[2]), "+f"(C[3])                      \
        : "r"(A[0]), "r"(A[1]), "r"(A[2]), "r"(A[3]), "r"(B[0]), "r"(B[1]))

// ---------------- tensor-core GEMM: g_X0 = X @ W, 3-term split-bf16 ----------------
__global__ __launch_bounds__(256) void k_gemm(const float* __restrict__ A) {
    __shared__ unsigned As_h[128][17], As_l[128][17];
    __shared__ unsigned Bs_h[128][17], Bs_l[128][17];

    const int tid = threadIdx.x;
    const int wid = tid >> 5, lane = tid & 31;
    const int g = lane >> 2, t = lane & 3;
    const int warpM = wid & 3, warpN = wid >> 2;
    const int rowBase = blockIdx.y * 128;
    const int colBase = blockIdx.x * 128;

    float c[2][8][4];
#pragma unroll
    for (int mt = 0; mt < 2; mt++)
#pragma unroll
        for (int nt = 0; nt < 8; nt++)
#pragma unroll
            for (int r = 0; r < 4; r++) c[mt][nt][r] = 0.f;

    const int lrow = tid >> 1;
    const int lko  = (tid & 1) * 16;
    const int lpo  = (tid & 1) * 8;
    const bool aval = (rowBase + lrow) < NV;
    const float* aBase = A + (size_t)(rowBase + lrow) * IN_CH + lko;
    const int bn = tid >> 1;

    for (int k0 = 0; k0 < IN_CH; k0 += 32) {
#pragma unroll
        for (int j = 0; j < 4; j++) {
            float4 v = make_float4(0.f, 0.f, 0.f, 0.f);
            if (aval) v = *(const float4*)(aBase + k0 + j * 4);
            unsigned h0, l0, h1, l1;
            split2(v.x, v.y, h0, l0);
            split2(v.z, v.w, h1, l1);
            As_h[lrow][lpo + j * 2]     = h0;
            As_h[lrow][lpo + j * 2 + 1] = h1;
            As_l[lrow][lpo + j * 2]     = l0;
            As_l[lrow][lpo + j * 2 + 1] = l1;
        }
        {
            int p0 = k0 >> 1;
            const unsigned* src_h = &g_Wt_hi[(size_t)(colBase + bn) * 128 + p0 + lpo];
            const unsigned* src_l = &g_Wt_lo[(size_t)(colBase + bn) * 128 + p0 + lpo];
            uint4 h0 = ((const uint4*)src_h)[0];
            uint4 h1 = ((const uint4*)src_h)[1];
            uint4 l0 = ((const uint4*)src_l)[0];
            uint4 l1 = ((const uint4*)src_l)[1];
            Bs_h[bn][lpo + 0] = h0.x; Bs_h[bn][lpo + 1] = h0.y;
            Bs_h[bn][lpo + 2] = h0.z; Bs_h[bn][lpo + 3] = h0.w;
            Bs_h[bn][lpo + 4] = h1.x; Bs_h[bn][lpo + 5] = h1.y;
            Bs_h[bn][lpo + 6] = h1.z; Bs_h[bn][lpo + 7] = h1.w;
            Bs_l[bn][lpo + 0] = l0.x; Bs_l[bn][lpo + 1] = l0.y;
            Bs_l[bn][lpo + 2] = l0.z; Bs_l[bn][lpo + 3] = l0.w;
            Bs_l[bn][lpo + 4] = l1.x; Bs_l[bn][lpo + 5] = l1.y;
            Bs_l[bn][lpo + 6] = l1.z; Bs_l[bn][lpo + 7] = l1.w;
        }
        __syncthreads();

#pragma unroll
        for (int s = 0; s < 2; s++) {
            const int pb = s * 8;
            unsigned ah[2][4], al[2][4];
#pragma unroll
            for (int mt = 0; mt < 2; mt++) {
                int r = warpM * 32 + mt * 16;
                ah[mt][0] = As_h[r + g][pb + t];
                ah[mt][1] = As_h[r + g + 8][pb + t];
                ah[mt][2] = As_h[r + g][pb + t + 4];
                ah[mt][3] = As_h[r + g + 8][pb + t + 4];
                al[mt][0] = As_l[r + g][pb + t];
                al[mt][1] = As_l[r + g + 8][pb + t];
                al[mt][2] = As_l[r + g][pb + t + 4];
                al[mt][3] = As_l[r + g + 8][pb + t + 4];
            }
            unsigned bh[8][2], bl[8][2];
#pragma unroll
            for (int nt = 0; nt < 8; nt++) {
                int n = warpN * 64 + nt * 8 + g;
                bh[nt][0] = Bs_h[n][pb + t];
                bh[nt][1] = Bs_h[n][pb + t + 4];
                bl[nt][0] = Bs_l[n][pb + t];
                bl[nt][1] = Bs_l[n][pb + t + 4];
            }
#pragma unroll
            for (int mt = 0; mt < 2; mt++)
#pragma unroll
                for (int nt = 0; nt < 8; nt++) {
                    MMA_BF16(c[mt][nt], ah[mt], bh[nt]);
                    MMA_BF16(c[mt][nt], ah[mt], bl[nt]);
                    MMA_BF16(c[mt][nt], al[mt], bh[nt]);
                }
        }
        __syncthreads();
    }

#pragma unroll
    for (int mt = 0; mt < 2; mt++) {
        int r0 = rowBase + warpM * 32 + mt * 16 + g;
#pragma unroll
        for (int nt = 0; nt < 8; nt++) {
            int cc = colBase + warpN * 64 + nt * 8 + 2 * t;
            if (r0 < NV)
                *(float2*)&g_X0[(size_t)r0 * HC + cc] = make_float2(c[mt][nt][0], c[mt][nt][1]);
            if (r0 + 8 < NV)
                *(float2*)&g_X0[(size_t)(r0 + 8) * HC + cc] = make_float2(c[mt][nt][2], c[mt][nt][3]);
        }
    }
}

// ---------------- init / histogram / scan / fill ----------------
__global__ void k_init() {
    int i = blockIdx.x * blockDim.x + threadIdx.x;
    if (i < NM) g_cntE[i] = 0;
    if (i < NV) g_cntV[i] = 0;
}

__global__ void k_hist(const int* __restrict__ vertex, const int* __restrict__ edges) {
    int e = blockIdx.x * blockDim.x + threadIdx.x;
    if (e >= NE) return;
    atomicAdd(&g_cntE[__ldg(&edges[e])], 1);
    atomicAdd(&g_cntV[__ldg(&vertex[e])], 1);
}

__global__ void k_scanA() {
    bool isE = (blockIdx.x < NBLK_E);
    int lb = isE ? blockIdx.x : blockIdx.x - NBLK_E;
    int n = isE ? NM : NV;
    const int* cnt = isE ? g_cntE : g_cntV;
    int* blkSum = isE ? g_blkSumE : g_blkSumV;

    int i4 = lb * 1024 + threadIdx.x;
    int s = 0;
    if (i4 * 4 < n) {
        int4 c = ((const int4*)cnt)[i4];
        s = c.x + c.y + c.z + c.w;
    }
    __shared__ int ws[32];
    int lane = threadIdx.x & 31, wid = threadIdx.x >> 5;
#pragma unroll
    for (int o = 16; o > 0; o >>= 1) s += __shfl_xor_sync(0xffffffffu, s, o);
    if (lane == 0) ws[wid] = s;
    __syncthreads();
    if (wid == 0) {
        int tv = ws[lane];
#pragma unroll
        for (int o = 16; o > 0; o >>= 1) tv += __shfl_xor_sync(0xffffffffu, tv, o);
        if (lane == 0) blkSum[lb] = tv;
    }
}

__global__ void k_scanB() {
    int lane = threadIdx.x & 31, wid = threadIdx.x >> 5;
    if (wid == 0) {
        int v = (lane < NBLK_E) ? g_blkSumE[lane] : 0;
        int incl = v;
#pragma unroll
        for (int o = 1; o < 32; o <<= 1) {
            int t = __shfl_up_sync(0xffffffffu, incl, o);
            if (lane >= o) incl += t;
        }
        if (lane < NBLK_E) g_blkOffE[lane] = incl - v;
        if (lane == 31) g_startE[NM] = incl;
    } else if (wid == 1) {
        int v = (lane < NBLK_V) ? g_blkSumV[lane] : 0;
        int incl = v;
#pragma unroll
        for (int o = 1; o < 32; o <<= 1) {
            int t = __shfl_up_sync(0xffffffffu, incl, o);
            if (lane >= o) incl += t;
        }
        if (lane < NBLK_V) g_blkOffV[lane] = incl - v;
        if (lane == 31) g_startV[NV] = incl;
    }
}

__global__ void k_scanC() {
    bool isE = (blockIdx.x < NBLK_E);
    int lb = isE ? blockIdx.x : blockIdx.x - NBLK_E;
    int n = isE ? NM : NV;
    const int* cnt = isE ? g_cntE : g_cntV;
    int* start = isE ? g_startE : g_startV;
    int* cur   = isE ? g_curE : g_curV;
    int blkOff = isE ? g_blkOffE[lb] : g_blkOffV[lb];

    int i4 = lb * 1024 + threadIdx.x;
    int4 c = make_int4(0, 0, 0, 0);
    if (i4 * 4 < n) c = ((const int4*)cnt)[i4];
    int tsum = c.x + c.y + c.z + c.w;

    __shared__ int ws[32];
    int lane = threadIdx.x & 31, wid = threadIdx.x >> 5;
    int incl = tsum;
#pragma unroll
    for (int o = 1; o < 32; o <<= 1) {
        int t = __shfl_up_sync(0xffffffffu, incl, o);
        if (lane >= o) incl += t;
    }
    if (lane == 31) ws[wid] = incl;
    __syncthreads();
    if (wid == 0) {
        int w = ws[lane];
#pragma unroll
        for (int o = 1; o < 32; o <<= 1) {
            int t = __shfl_up_sync(0xffffffffu, w, o);
            if (lane >= o) w += t;
        }
        ws[lane] = w;
    }
    __syncthreads();
    int excl = incl - tsum + (wid > 0 ? ws[wid - 1] : 0) + blkOff;

    if (i4 * 4 < n) {
        int4 st;
        st.x = excl;
        st.y = st.x + c.x;
        st.z = st.y + c.y;
        st.w = st.z + c.z;
        ((int4*)start)[i4] = st;
        ((int4*)cur)[i4]   = st;
    }
}

__global__ void k_fill(const int* __restrict__ vertex, const int* __restrict__ edges) {
    int e = blockIdx.x * blockDim.x + threadIdx.x;
    if (e >= NE) return;
    int v  = __ldg(&vertex[e]);
    int ed = __ldg(&edges[e]);
    int pE = atomicAdd(&g_curE[ed], 1);
    g_incE[pE] = v;
    int pV = atomicAdd(&g_curV[v], 1);
    g_incV[pV] = ed;
}

#define ACC4(A, X, W)                                                       \
    A.x += X.x * W; A.y += X.y * W; A.z += X.z * W; A.w += X.w * W;

// ---------------- per-hyperedge aggregate (mean, fp32 acc -> fp16 store) + logits ----------------
// Coalesced reads: lane covers X0 float4 `lane` and `lane+32`.
__global__ void k_edge_agg(const float* __restrict__ att) {
    int m = (blockIdx.x * blockDim.x + threadIdx.x) >> 5;
    if (m >= NM) return;
    int lane = threadIdx.x & 31;
    int s0 = g_startE[m], s1 = g_startE[m + 1];

    float4 acc0 = make_float4(0.f, 0.f, 0.f, 0.f);
    float4 acc1 = make_float4(0.f, 0.f, 0.f, 0.f);
    int i = s0;
    for (; i + 2 <= s1; i += 2) {
        int v0 = __ldg(&g_incE[i]);
        int v1 = __ldg(&g_incE[i + 1]);
        const float4* xr0 = (const float4*)&g_X0[(size_t)v0 * HC];
        const float4* xr1 = (const float4*)&g_X0[(size_t)v1 * HC];
        float4 xa0 = __ldg(&xr0[lane]), xa1 = __ldg(&xr0[lane + 32]);
        float4 xb0 = __ldg(&xr1[lane]), xb1 = __ldg(&xr1[lane + 32]);
        ACC4(acc0, xa0, 1.0f); ACC4(acc1, xa1, 1.0f);
        ACC4(acc0, xb0, 1.0f); ACC4(acc1, xb1, 1.0f);
    }
    if (i < s1) {
        int v0 = __ldg(&g_incE[i]);
        const float4* xr0 = (const float4*)&g_X0[(size_t)v0 * HC];
        float4 xa0 = __ldg(&xr0[lane]), xa1 = __ldg(&xr0[lane + 32]);
        ACC4(acc0, xa0, 1.0f); ACC4(acc1, xa1, 1.0f);
    }

    float inv = 1.0f / fmaxf((float)(s1 - s0), 1.0f);
    acc0.x *= inv; acc0.y *= inv; acc0.z *= inv; acc0.w *= inv;
    acc1.x *= inv; acc1.y *= inv; acc1.z *= inv; acc1.w *= inv;

    // store fp16: acc0 -> channels [4*lane,4*lane+4), acc1 -> [128+4*lane, ...)
    {
        __half2 h00 = __floats2half2_rn(acc0.x, acc0.y);
        __half2 h01 = __floats2half2_rn(acc0.z, acc0.w);
        __half2 h10 = __floats2half2_rn(acc1.x, acc1.y);
        __half2 h11 = __floats2half2_rn(acc1.z, acc1.w);
        uint2* xeA = (uint2*)&g_Xe[(size_t)m * HC];
        uint2* xeB = (uint2*)&g_Xe[(size_t)m * HC + 128];
        xeA[lane] = make_uint2(*(unsigned*)&h00, *(unsigned*)&h01);
        xeB[lane] = make_uint2(*(unsigned*)&h10, *(unsigned*)&h11);
    }

    // logits from fp32 accumulators (exact): acc0 head lane>>3, acc1 head 4+(lane>>3)
    const float4* at = (const float4*)att;
    float4 b0 = __ldg(&at[lane]), b1 = __ldg(&at[lane + 32]);
    float p0 = acc0.x * b0.x + acc0.y * b0.y + acc0.z * b0.z + acc0.w * b0.w;
    float p1 = acc1.x * b1.x + acc1.y * b1.y + acc1.z * b1.z + acc1.w * b1.w;
#pragma unroll
    for (int o = 1; o <= 4; o <<= 1) {
        p0 += __shfl_xor_sync(0xffffffffu, p0, o);
        p1 += __shfl_xor_sync(0xffffffffu, p1, o);
    }
    if ((lane & 7) == 0) {
        g_alphae[m * NH + (lane >> 3)]     = p0;
        g_alphae[m * NH + 4 + (lane >> 3)] = p1;
    }
}

__device__ __forceinline__ float gelu1(float x) {
    return 0.5f * x * (1.0f + erff(x * 0.70710678118654752f));
}

// ---------------- fused per-vertex online-softmax + fp16 weighted gather + GELU ----------------
// Gather: one uint4 per lane covers halves [8*lane, 8*lane+8) -> head = lane>>2.
__global__ void k_vertex(float* __restrict__ out) {
    int warp = (blockIdx.x * blockDim.x + threadIdx.x) >> 5;
    if (warp >= NV) return;
    int lane = threadIdx.x & 31;

    int v0i = g_startV[warp], v1i = g_startV[warp + 1];
    int deg = v1i - v0i;

    int h = lane & 7, islot = lane >> 3;

    // online (max, sum) over this lane's subset for head h
    float m = -INFINITY, s = 0.f;
    for (int i = islot; i < deg; i += 4) {
        int ed = __ldg(&g_incV[v0i + i]);
        float a = g_alphae[ed * NH + h];
        a = a >= 0.f ? a : 0.2f * a;
        float mn = fmaxf(m, a);
        s = s * __expf(m - mn) + __expf(a - mn);
        m = mn;
    }
#pragma unroll
    for (int off = 8; off <= 16; off <<= 1) {
        float m2 = __shfl_xor_sync(0xffffffffu, m, off);
        float s2 = __shfl_xor_sync(0xffffffffu, s, off);
        float mn = fmaxf(m, m2);
        float sn = 0.f;
        if (s  > 0.f) sn += s  * __expf(m  - mn);
        if (s2 > 0.f) sn += s2 * __expf(m2 - mn);
        m = mn; s = sn;
    }

    int hh = lane >> 2;
    float m_t = __shfl_sync(0xffffffffu, m, hh);
    float s_t = __shfl_sync(0xffffffffu, s, hh);
    float rs = 1.0f / (s_t + 1e-16f);

    float4 acc0 = make_float4(0.f, 0.f, 0.f, 0.f);
    float4 acc1 = make_float4(0.f, 0.f, 0.f, 0.f);
    int i = 0;
    for (; i + 2 <= deg; i += 2) {
        int e0 = __ldg(&g_incV[v0i + i]);
        int e1 = __ldg(&g_incV[v0i + i + 1]);
        float a0 = g_alphae[e0 * NH + hh];
        float a1 = g_alphae[e1 * NH + hh];
        const uint4* xr0 = (const uint4*)&g_Xe[(size_t)e0 * HC];
        const uint4* xr1 = (const uint4*)&g_Xe[(size_t)e1 * HC];
        uint4 ra = __ldg(&xr0[lane]);
        uint4 rb = __ldg(&xr1[lane]);
        a0 = a0 >= 0.f ? a0 : 0.2f * a0;
        a1 = a1 >= 0.f ? a1 : 0.2f * a1;
        float w0 = __expf(a0 - m_t) * rs;
        float w1 = __expf(a1 - m_t) * rs;
        float2 t0;
        t0 = __half22float2(*(__half2*)&ra.x); acc0.x += t0.x * w0; acc0.y += t0.y * w0;
        t0 = __half22float2(*(__half2*)&ra.y); acc0.z += t0.x * w0; acc0.w += t0.y * w0;
        t0 = __half22float2(*(__half2*)&ra.z); acc1.x += t0.x * w0; acc1.y += t0.y * w0;
        t0 = __half22float2(*(__half2*)&ra.w); acc1.z += t0.x * w0; acc1.w += t0.y * w0;
        t0 = __half22float2(*(__half2*)&rb.x); acc0.x += t0.x * w1; acc0.y += t0.y * w1;
        t0 = __half22float2(*(__half2*)&rb.y); acc0.z += t0.x * w1; acc0.w += t0.y * w1;
        t0 = __half22float2(*(__half2*)&rb.z); acc1.x += t0.x * w1; acc1.y += t0.y * w1;
        t0 = __half22float2(*(__half2*)&rb.w); acc1.z += t0.x * w1; acc1.w += t0.y * w1;
    }
    if (i < deg) {
        int e0 = __ldg(&g_incV[v0i + i]);
        float a0 = g_alphae[e0 * NH + hh];
        const uint4* xr0 = (const uint4*)&g_Xe[(size_t)e0 * HC];
        uint4 ra = __ldg(&xr0[lane]);
        a0 = a0 >= 0.f ? a0 : 0.2f * a0;
        float w0 = __expf(a0 - m_t) * rs;
        float2 t0;
        t0 = __half22float2(*(__half2*)&ra.x); acc0.x += t0.x * w0; acc0.y += t0.y * w0;
        t0 = __half22float2(*(__half2*)&ra.y); acc0.z += t0.x * w0; acc0.w += t0.y * w0;
        t0 = __half22float2(*(__half2*)&ra.z); acc1.x += t0.x * w0; acc1.y += t0.y * w0;
        t0 = __half22float2(*(__half2*)&ra.w); acc1.z += t0.x * w0; acc1.w += t0.y * w0;
    }

    acc0.x = gelu1(acc0.x); acc0.y = gelu1(acc0.y);
    acc0.z = gelu1(acc0.z); acc0.w = gelu1(acc0.w);
    acc1.x = gelu1(acc1.x); acc1.y = gelu1(acc1.y);
    acc1.z = gelu1(acc1.z); acc1.w = gelu1(acc1.w);

    // channels [8*lane, 8*lane+8)
    float4* op = (float4*)&out[(size_t)warp * HC + 8 * lane];
    op[0] = acc0;
    op[1] = acc1;
}

extern "C" void kernel_launch(void* const* d_in, const int* in_sizes, int n_in,
                              void* d_out, int out_size) {
    const float* X      = (const float*)d_in[0];
    const float* W      = (const float*)d_in[1];
    const float* att    = (const float*)d_in[2];
    const int*   vertex = (const int*)d_in[3];
    const int*   edges  = (const int*)d_in[4];
    float* out = (float*)d_out;

    static cudaStream_t s2 = nullptr;
    static cudaEvent_t evFork = nullptr, evJoin = nullptr;
    if (s2 == nullptr) {
        cudaStreamCreate(&s2);
        cudaEventCreateWithFlags(&evFork, cudaEventDisableTiming);
        cudaEventCreateWithFlags(&evJoin, cudaEventDisableTiming);
    }

    // fork: GEMM (tensor core) on side stream, concurrent with CSR build
    cudaEventRecord(evFork, 0);
    cudaStreamWaitEvent(s2, evFork, 0);
    k_prepW<<<(HC * (IN_CH / 2) + 255) / 256, 256, 0, s2>>>(W);
    {
        dim3 grid(HC / 128, (NV + 127) / 128);
        k_gemm<<<grid, 256, 0, s2>>>(X);
    }
    k_init<<<(NM + 255) / 256, 256>>>();
    k_hist<<<(NE + 255) / 256, 256>>>(vertex, edges);
    k_scanA<<<NBLK_E + NBLK_V, 1024>>>();
    k_scanB<<<1, 64>>>();
    k_scanC<<<NBLK_E + NBLK_V, 1024>>>();
    k_fill<<<(NE + 255) / 256, 256>>>(vertex, edges);
    // join: edge aggregation needs both X0 (s2) and CSR (main)
    cudaEventRecord(evJoin, s2);
    cudaStreamWaitEvent(0, evJoin, 0);

    k_edge_agg<<<(NM * 32 + 255) / 256, 256>>>(att);
    k_vertex<<<(NV * 32 + 255) / 256, 256>>>(out);
}

// round 14
// speedup vs baseline: 1.2700x; 1.0890x over previous
#include <cuda_runtime.h>
#include <cuda_bf16.h>
#include <cuda_fp16.h>
#include <math.h>

#define NV 50000
#define NE 600000
#define NM 100000
#define IN_CH 256
#define HC 256
#define NH 8

#define SCAN_CHUNK 4096
#define NBLK_E ((NM + SCAN_CHUNK - 1) / SCAN_CHUNK)   // 25
#define NBLK_V ((NV + SCAN_CHUNK - 1) / SCAN_CHUNK)   // 13

// ---------------- scratch (device globals) ----------------
__device__ __half g_X0[NV * HC];        // X @ W (fp16)
__device__ __half g_Xe[NM * HC];        // hyperedge feature MEANS (fp16)
__device__ float  g_alphae[NM * NH];    // per-hyperedge logits (fp32)
__device__ int    g_cntE[NM], g_cntV[NV];
__device__ int    g_startE[NM + 1], g_startV[NV + 1];
__device__ int    g_curE[NM], g_curV[NV];
__device__ int    g_incE[NE];
__device__ int    g_incV[NE];
__device__ int    g_blkSumE[NBLK_E], g_blkSumV[NBLK_V];
__device__ int    g_blkOffE[NBLK_E], g_blkOffV[NBLK_V];
__device__ unsigned g_Wt_hi[HC * (IN_CH / 2)];
__device__ unsigned g_Wt_lo[HC * (IN_CH / 2)];

// ---------------- split helper: two floats -> packed bf16x2 hi + lo ----------------
__device__ __forceinline__ void split2(float x, float y, unsigned& h, unsigned& l) {
    __nv_bfloat16 hx = __float2bfloat16_rn(x);
    __nv_bfloat16 hy = __float2bfloat16_rn(y);
    float lxf = x - __bfloat162float(hx);
    float lyf = y - __bfloat162float(hy);
    __nv_bfloat16 lx = __float2bfloat16_rn(lxf);
    __nv_bfloat16 ly = __float2bfloat16_rn(lyf);
    h = ((unsigned)__bfloat16_as_ushort(hy) << 16) | (unsigned)__bfloat16_as_ushort(hx);
    l = ((unsigned)__bfloat16_as_ushort(ly) << 16) | (unsigned)__bfloat16_as_ushort(lx);
}

// ---------------- prep: split + transpose W ----------------
__global__ void k_prepW(const float* __restrict__ W) {
    int idx = blockIdx.x * blockDim.x + threadIdx.x;
    if (idx >= HC * (IN_CH / 2)) return;
    int n = idx >> 7, p = idx & 127;
    float x = __ldg(&W[(2 * p) * HC + n]);
    float y = __ldg(&W[(2 * p + 1) * HC + n]);
    unsigned h, l;
    split2(x, y, h, l);
    g_Wt_hi[idx] = h;
    g_Wt_lo[idx] = l;
}

#define MMA_BF16(C, A, B)                                                     \
    asm volatile(                                                             \
        "mma.sync.aligned.m16n8k16.row.col.f32.bf16.bf16.f32 "                \
        "{%0,%1,%2,%3}, {%4,%5,%6,%7}, {%8,%9}, {%0,%1,%2,%3};"               \
        : "+f"(C[0]), "+f"(C[1]), "+f"(C[2]), "+f"(C[3])                      \
        : "r"(A[0]), "r"(A[1]), "r"(A[2]), "r"(A[3]), "r"(B[0]), "r"(B[1]))

// ---------------- tensor-core GEMM: g_X0 = X @ W, 3-term split-bf16, fp16 store ----------------
__global__ __launch_bounds__(256) void k_gemm(const float* __restrict__ A) {
    __shared__ unsigned As_h[128][17], As_l[128][17];
    __shared__ unsigned Bs_h[128][17], Bs_l[128][17];

    const int tid = threadIdx.x;
    const int wid = tid >> 5, lane = tid & 31;
    const int g = lane >> 2, t = lane & 3;
    const int warpM = wid & 3, warpN = wid >> 2;
    const int rowBase = blockIdx.y * 128;
    const int colBase = blockIdx.x * 128;

    float c[2][8][4];
#pragma unroll
    for (int mt = 0; mt < 2; mt++)
#pragma unroll
        for (int nt = 0; nt < 8; nt++)
#pragma unroll
            for (int r = 0; r < 4; r++) c[mt][nt][r] = 0.f;

    const int lrow = tid >> 1;
    const int lko  = (tid & 1) * 16;
    const int lpo  = (tid & 1) * 8;
    const bool aval = (rowBase + lrow) < NV;
    const float* aBase = A + (size_t)(rowBase + lrow) * IN_CH + lko;
    const int bn = tid >> 1;

    for (int k0 = 0; k0 < IN_CH; k0 += 32) {
#pragma unroll
        for (int j = 0; j < 4; j++) {
            float4 v = make_float4(0.f, 0.f, 0.f, 0.f);
            if (aval) v = *(const float4*)(aBase + k0 + j * 4);
            unsigned h0, l0, h1, l1;
            split2(v.x, v.y, h0, l0);
            split2(v.z, v.w, h1, l1);
            As_h[lrow][lpo + j * 2]     = h0;
            As_h[lrow][lpo + j * 2 + 1] = h1;
            As_l[lrow][lpo + j * 2]     = l0;
            As_l[lrow][lpo + j * 2 + 1] = l1;
        }
        {
            int p0 = k0 >> 1;
            const unsigned* src_h = &g_Wt_hi[(size_t)(colBase + bn) * 128 + p0 + lpo];
            const unsigned* src_l = &g_Wt_lo[(size_t)(colBase + bn) * 128 + p0 + lpo];
            uint4 h0 = ((const uint4*)src_h)[0];
            uint4 h1 = ((const uint4*)src_h)[1];
            uint4 l0 = ((const uint4*)src_l)[0];
            uint4 l1 = ((const uint4*)src_l)[1];
            Bs_h[bn][lpo + 0] = h0.x; Bs_h[bn][lpo + 1] = h0.y;
            Bs_h[bn][lpo + 2] = h0.z; Bs_h[bn][lpo + 3] = h0.w;
            Bs_h[bn][lpo + 4] = h1.x; Bs_h[bn][lpo + 5] = h1.y;
            Bs_h[bn][lpo + 6] = h1.z; Bs_h[bn][lpo + 7] = h1.w;
            Bs_l[bn][lpo + 0] = l0.x; Bs_l[bn][lpo + 1] = l0.y;
            Bs_l[bn][lpo + 2] = l0.z; Bs_l[bn][lpo + 3] = l0.w;
            Bs_l[bn][lpo + 4] = l1.x; Bs_l[bn][lpo + 5] = l1.y;
            Bs_l[bn][lpo + 6] = l1.z; Bs_l[bn][lpo + 7] = l1.w;
        }
        __syncthreads();

#pragma unroll
        for (int s = 0; s < 2; s++) {
            const int pb = s * 8;
            unsigned ah[2][4], al[2][4];
#pragma unroll
            for (int mt = 0; mt < 2; mt++) {
                int r = warpM * 32 + mt * 16;
                ah[mt][0] = As_h[r + g][pb + t];
                ah[mt][1] = As_h[r + g + 8][pb + t];
                ah[mt][2] = As_h[r + g][pb + t + 4];
                ah[mt][3] = As_h[r + g + 8][pb + t + 4];
                al[mt][0] = As_l[r + g][pb + t];
                al[mt][1] = As_l[r + g + 8][pb + t];
                al[mt][2] = As_l[r + g][pb + t + 4];
                al[mt][3] = As_l[r + g + 8][pb + t + 4];
            }
            unsigned bh[8][2], bl[8][2];
#pragma unroll
            for (int nt = 0; nt < 8; nt++) {
                int n = warpN * 64 + nt * 8 + g;
                bh[nt][0] = Bs_h[n][pb + t];
                bh[nt][1] = Bs_h[n][pb + t + 4];
                bl[nt][0] = Bs_l[n][pb + t];
                bl[nt][1] = Bs_l[n][pb + t + 4];
            }
#pragma unroll
            for (int mt = 0; mt < 2; mt++)
#pragma unroll
                for (int nt = 0; nt < 8; nt++) {
                    MMA_BF16(c[mt][nt], ah[mt], bh[nt]);
                    MMA_BF16(c[mt][nt], ah[mt], bl[nt]);
                    MMA_BF16(c[mt][nt], al[mt], bh[nt]);
                }
        }
        __syncthreads();
    }

#pragma unroll
    for (int mt = 0; mt < 2; mt++) {
        int r0 = rowBase + warpM * 32 + mt * 16 + g;
#pragma unroll
        for (int nt = 0; nt < 8; nt++) {
            int cc = colBase + warpN * 64 + nt * 8 + 2 * t;
            if (r0 < NV) {
                __half2 hv = __floats2half2_rn(c[mt][nt][0], c[mt][nt][1]);
                *(__half2*)&g_X0[(size_t)r0 * HC + cc] = hv;
            }
            if (r0 + 8 < NV) {
                __half2 hv = __floats2half2_rn(c[mt][nt][2], c[mt][nt][3]);
                *(__half2*)&g_X0[(size_t)(r0 + 8) * HC + cc] = hv;
            }
        }
    }
}

// ---------------- init / histogram / scan / fill ----------------
__global__ void k_init() {
    int i = blockIdx.x * blockDim.x + threadIdx.x;
    if (i < NM) g_cntE[i] = 0;
    if (i < NV) g_cntV[i] = 0;
}

__global__ void k_hist(const int* __restrict__ vertex, const int* __restrict__ edges) {
    int e = blockIdx.x * blockDim.x + threadIdx.x;
    if (e >= NE) return;
    atomicAdd(&g_cntE[__ldg(&edges[e])], 1);
    atomicAdd(&g_cntV[__ldg(&vertex[e])], 1);
}

__global__ void k_scanA() {
    bool isE = (blockIdx.x < NBLK_E);
    int lb = isE ? blockIdx.x : blockIdx.x - NBLK_E;
    int n = isE ? NM : NV;
    const int* cnt = isE ? g_cntE : g_cntV;
    int* blkSum = isE ? g_blkSumE : g_blkSumV;

    int i4 = lb * 1024 + threadIdx.x;
    int s = 0;
    if (i4 * 4 < n) {
        int4 c = ((const int4*)cnt)[i4];
        s = c.x + c.y + c.z + c.w;
    }
    __shared__ int ws[32];
    int lane = threadIdx.x & 31, wid = threadIdx.x >> 5;
#pragma unroll
    for (int o = 16; o > 0; o >>= 1) s += __shfl_xor_sync(0xffffffffu, s, o);
    if (lane == 0) ws[wid] = s;
    __syncthreads();
    if (wid == 0) {
        int tv = ws[lane];
#pragma unroll
        for (int o = 16; o > 0; o >>= 1) tv += __shfl_xor_sync(0xffffffffu, tv, o);
        if (lane == 0) blkSum[lb] = tv;
    }
}

__global__ void k_scanB() {
    int lane = threadIdx.x & 31, wid = threadIdx.x >> 5;
    if (wid == 0) {
        int v = (lane < NBLK_E) ? g_blkSumE[lane] : 0;
        int incl = v;
#pragma unroll
        for (int o = 1; o < 32; o <<= 1) {
            int t = __shfl_up_sync(0xffffffffu, incl, o);
            if (lane >= o) incl += t;
        }
        if (lane < NBLK_E) g_blkOffE[lane] = incl - v;
        if (lane == 31) g_startE[NM] = incl;
    } else if (wid == 1) {
        int v = (lane < NBLK_V) ? g_blkSumV[lane] : 0;
        int incl = v;
#pragma unroll
        for (int o = 1; o < 32; o <<= 1) {
            int t = __shfl_up_sync(0xffffffffu, incl, o);
            if (lane >= o) incl += t;
        }
        if (lane < NBLK_V) g_blkOffV[lane] = incl - v;
        if (lane == 31) g_startV[NV] = incl;
    }
}

__global__ void k_scanC() {
    bool isE = (blockIdx.x < NBLK_E);
    int lb = isE ? blockIdx.x : blockIdx.x - NBLK_E;
    int n = isE ? NM : NV;
    const int* cnt = isE ? g_cntE : g_cntV;
    int* start = isE ? g_startE : g_startV;
    int* cur   = isE ? g_curE : g_curV;
    int blkOff = isE ? g_blkOffE[lb] : g_blkOffV[lb];

    int i4 = lb * 1024 + threadIdx.x;
    int4 c = make_int4(0, 0, 0, 0);
    if (i4 * 4 < n) c = ((const int4*)cnt)[i4];
    int tsum = c.x + c.y + c.z + c.w;

    __shared__ int ws[32];
    int lane = threadIdx.x & 31, wid = threadIdx.x >> 5;
    int incl = tsum;
#pragma unroll
    for (int o = 1; o < 32; o <<= 1) {
        int t = __shfl_up_sync(0xffffffffu, incl, o);
        if (lane >= o) incl += t;
    }
    if (lane == 31) ws[wid] = incl;
    __syncthreads();
    if (wid == 0) {
        int w = ws[lane];
#pragma unroll
        for (int o = 1; o < 32; o <<= 1) {
            int t = __shfl_up_sync(0xffffffffu, w, o);
            if (lane >= o) w += t;
        }
        ws[lane] = w;
    }
    __syncthreads();
    int excl = incl - tsum + (wid > 0 ? ws[wid - 1] : 0) + blkOff;

    if (i4 * 4 < n) {
        int4 st;
        st.x = excl;
        st.y = st.x + c.x;
        st.z = st.y + c.y;
        st.w = st.z + c.z;
        ((int4*)start)[i4] = st;
        ((int4*)cur)[i4]   = st;
    }
}

__global__ void k_fill(const int* __restrict__ vertex, const int* __restrict__ edges) {
    int e = blockIdx.x * blockDim.x + threadIdx.x;
    if (e >= NE) return;
    int v  = __ldg(&vertex[e]);
    int ed = __ldg(&edges[e]);
    int pE = atomicAdd(&g_curE[ed], 1);
    g_incE[pE] = v;
    int pV = atomicAdd(&g_curV[v], 1);
    g_incV[pV] = ed;
}

// accumulate 8 halves (uint4) into acc0/acc1 with weight W
#define ACCH8(A0, A1, R, W)                                                   \
    {                                                                         \
        float2 _t;                                                            \
        _t = __half22float2(*(__half2*)&R.x); A0.x += _t.x * W; A0.y += _t.y * W; \
        _t = __half22float2(*(__half2*)&R.y); A0.z += _t.x * W; A0.w += _t.y * W; \
        _t = __half22float2(*(__half2*)&R.z); A1.x += _t.x * W; A1.y += _t.y * W; \
        _t = __half22float2(*(__half2*)&R.w); A1.z += _t.x * W; A1.w += _t.y * W; \
    }

// ---------------- per-hyperedge aggregate (fp16 rows, fp32 acc) + logits ----------------
// Lane covers channels [8*lane, 8*lane+8) -> head = lane>>2; one uint4 per row per lane.
__global__ void k_edge_agg(const float* __restrict__ att) {
    int m = (blockIdx.x * blockDim.x + threadIdx.x) >> 5;
    if (m >= NM) return;
    int lane = threadIdx.x & 31;
    int s0 = g_startE[m], s1 = g_startE[m + 1];

    float4 acc0 = make_float4(0.f, 0.f, 0.f, 0.f);
    float4 acc1 = make_float4(0.f, 0.f, 0.f, 0.f);
    int i = s0;
    for (; i + 2 <= s1; i += 2) {
        int v0 = __ldg(&g_incE[i]);
        int v1 = __ldg(&g_incE[i + 1]);
        const uint4* xr0 = (const uint4*)&g_X0[(size_t)v0 * HC];
        const uint4* xr1 = (const uint4*)&g_X0[(size_t)v1 * HC];
        uint4 ra = __ldg(&xr0[lane]);
        uint4 rb = __ldg(&xr1[lane]);
        ACCH8(acc0, acc1, ra, 1.0f);
        ACCH8(acc0, acc1, rb, 1.0f);
    }
    if (i < s1) {
        int v0 = __ldg(&g_incE[i]);
        const uint4* xr0 = (const uint4*)&g_X0[(size_t)v0 * HC];
        uint4 ra = __ldg(&xr0[lane]);
        ACCH8(acc0, acc1, ra, 1.0f);
    }

    float inv = 1.0f / fmaxf((float)(s1 - s0), 1.0f);
    acc0.x *= inv; acc0.y *= inv; acc0.z *= inv; acc0.w *= inv;
    acc1.x *= inv; acc1.y *= inv; acc1.z *= inv; acc1.w *= inv;

    // store fp16: channels [8*lane, 8*lane+8)
    {
        __half2 h00 = __floats2half2_rn(acc0.x, acc0.y);
        __half2 h01 = __floats2half2_rn(acc0.z, acc0.w);
        __half2 h10 = __floats2half2_rn(acc1.x, acc1.y);
        __half2 h11 = __floats2half2_rn(acc1.z, acc1.w);
        uint4* xe = (uint4*)&g_Xe[(size_t)m * HC];
        xe[lane] = make_uint4(*(unsigned*)&h00, *(unsigned*)&h01,
                              *(unsigned*)&h10, *(unsigned*)&h11);
    }

    // logits from fp32 accumulators; head = lane>>2, reduce over 4-lane group
    const float4* at = (const float4*)att;
    float4 b0 = __ldg(&at[lane * 2]), b1 = __ldg(&at[lane * 2 + 1]);
    float p = acc0.x * b0.x + acc0.y * b0.y + acc0.z * b0.z + acc0.w * b0.w
            + acc1.x * b1.x + acc1.y * b1.y + acc1.z * b1.z + acc1.w * b1.w;
    p += __shfl_xor_sync(0xffffffffu, p, 1);
    p += __shfl_xor_sync(0xffffffffu, p, 2);
    if ((lane & 3) == 0) g_alphae[m * NH + (lane >> 2)] = p;
}

__device__ __forceinline__ float gelu1(float x) {
    return 0.5f * x * (1.0f + erff(x * 0.70710678118654752f));
}

// ---------------- fused per-vertex online-softmax + fp16 weighted gather + GELU ----------------
// Gather: one uint4 per lane covers halves [8*lane, 8*lane+8) -> head = lane>>2.
__global__ void k_vertex(float* __restrict__ out) {
    int warp = (blockIdx.x * blockDim.x + threadIdx.x) >> 5;
    if (warp >= NV) return;
    int lane = threadIdx.x & 31;

    int v0i = g_startV[warp], v1i = g_startV[warp + 1];
    int deg = v1i - v0i;

    int h = lane & 7, islot = lane >> 3;

    // online (max, sum) over this lane's subset for head h
    float m = -INFINITY, s = 0.f;
    for (int i = islot; i < deg; i += 4) {
        int ed = __ldg(&g_incV[v0i + i]);
        float a = g_alphae[ed * NH + h];
        a = a >= 0.f ? a : 0.2f * a;
        float mn = fmaxf(m, a);
        s = s * __expf(m - mn) + __expf(a - mn);
        m = mn;
    }
#pragma unroll
    for (int off = 8; off <= 16; off <<= 1) {
        float m2 = __shfl_xor_sync(0xffffffffu, m, off);
        float s2 = __shfl_xor_sync(0xffffffffu, s, off);
        float mn = fmaxf(m, m2);
        float sn = 0.f;
        if (s  > 0.f) sn += s  * __expf(m  - mn);
        if (s2 > 0.f) sn += s2 * __expf(m2 - mn);
        m = mn; s = sn;
    }

    int hh = lane >> 2;
    float m_t = __shfl_sync(0xffffffffu, m, hh);
    float s_t = __shfl_sync(0xffffffffu, s, hh);
    float rs = 1.0f / (s_t + 1e-16f);

    float4 acc0 = make_float4(0.f, 0.f, 0.f, 0.f);
    float4 acc1 = make_float4(0.f, 0.f, 0.f, 0.f);
    int i = 0;
    for (; i + 2 <= deg; i += 2) {
        int e0 = __ldg(&g_incV[v0i + i]);
        int e1 = __ldg(&g_incV[v0i + i + 1]);
        float a0 = g_alphae[e0 * NH + hh];
        float a1 = g_alphae[e1 * NH + hh];
        const uint4* xr0 = (const uint4*)&g_Xe[(size_t)e0 * HC];
        const uint4* xr1 = (const uint4*)&g_Xe[(size_t)e1 * HC];
        uint4 ra = __ldg(&xr0[lane]);
        uint4 rb = __ldg(&xr1[lane]);
        a0 = a0 >= 0.f ? a0 : 0.2f * a0;
        a1 = a1 >= 0.f ? a1 : 0.2f * a1;
        float w0 = __expf(a0 - m_t) * rs;
        float w1 = __expf(a1 - m_t) * rs;
        ACCH8(acc0, acc1, ra, w0);
        ACCH8(acc0, acc1, rb, w1);
    }
    if (i < deg) {
        int e0 = __ldg(&g_incV[v0i + i]);
        float a0 = g_alphae[e0 * NH + hh];
        const uint4* xr0 = (const uint4*)&g_Xe[(size_t)e0 * HC];
        uint4 ra = __ldg(&xr0[lane]);
        a0 = a0 >= 0.f ? a0 : 0.2f * a0;
        float w0 = __expf(a0 - m_t) * rs;
        ACCH8(acc0, acc1, ra, w0);
    }

    acc0.x = gelu1(acc0.x); acc0.y = gelu1(acc0.y);
    acc0.z = gelu1(acc0.z); acc0.w = gelu1(acc0.w);
    acc1.x = gelu1(acc1.x); acc1.y = gelu1(acc1.y);
    acc1.z = gelu1(acc1.z); acc1.w = gelu1(acc1.w);

    // channels [8*lane, 8*lane+8)
    float4* op = (float4*)&out[(size_t)warp * HC + 8 * lane];
    op[0] = acc0;
    op[1] = acc1;
}

extern "C" void kernel_launch(void* const* d_in, const int* in_sizes, int n_in,
                              void* d_out, int out_size) {
    const float* X      = (const float*)d_in[0];
    const float* W      = (const float*)d_in[1];
    const float* att    = (const float*)d_in[2];
    const int*   vertex = (const int*)d_in[3];
    const int*   edges  = (const int*)d_in[4];
    float* out = (float*)d_out;

    static cudaStream_t s2 = nullptr;
    static cudaEvent_t evFork = nullptr, evJoin = nullptr;
    if (s2 == nullptr) {
        cudaStreamCreate(&s2);
        cudaEventCreateWithFlags(&evFork, cudaEventDisableTiming);
        cudaEventCreateWithFlags(&evJoin, cudaEventDisableTiming);
    }

    // fork: GEMM (tensor core) on side stream, concurrent with CSR build
    cudaEventRecord(evFork, 0);
    cudaStreamWaitEvent(s2, evFork, 0);
    k_prepW<<<(HC * (IN_CH / 2) + 255) / 256, 256, 0, s2>>>(W);
    {
        dim3 grid(HC / 128, (NV + 127) / 128);
        k_gemm<<<grid, 256, 0, s2>>>(X);
    }
    k_init<<<(NM + 255) / 256, 256>>>();
    k_hist<<<(NE + 255) / 256, 256>>>(vertex, edges);
    k_scanA<<<NBLK_E + NBLK_V, 1024>>>();
    k_scanB<<<1, 64>>>();
    k_scanC<<<NBLK_E + NBLK_V, 1024>>>();
    k_fill<<<(NE + 255) / 256, 256>>>(vertex, edges);
    // join: edge aggregation needs both X0 (s2) and CSR (main)
    cudaEventRecord(evJoin, s2);
    cudaStreamWaitEvent(0, evJoin, 0);

    k_edge_agg<<<(NM * 32 + 255) / 256, 256>>>(att);
    k_vertex<<<(NV * 32 + 255) / 256, 256>>>(out);
}